// round 2
// baseline (speedup 1.0000x reference)
#include <cuda_runtime.h>

#define NB 8
#define HW 4096
#define CI 256
#define CA 128
#define CO 256
#define BI 64
#define BJ 64
#define QSTR 129
#define SSTR 65
// 1/(1e-8 + sqrt(128))
#define INVS 0.08838834764831843f

// Scratch (allocation-free: __device__ globals)
__device__ float g_q[NB * HW * CA];      // [n][pos][128]
__device__ float g_feat[NB * HW * CO];   // [n][pos][256]
__device__ float g_scale[CO + CA];
__device__ float g_bias[CO + CA];

// ---------------------------------------------------------------------------
// Fold BN into per-channel scale/bias: y = conv*scale + bias, then ReLU.
// Channels [0,256) = reduc (feat), [256,384) = att (q).
// ---------------------------------------------------------------------------
__global__ void prep_kernel(const float* __restrict__ rg, const float* __restrict__ rb,
                            const float* __restrict__ rm, const float* __restrict__ rv,
                            const float* __restrict__ ag, const float* __restrict__ ab,
                            const float* __restrict__ am, const float* __restrict__ av) {
    int o = threadIdx.x;
    if (o < CO) {
        float inv = rg[o] * rsqrtf(rv[o] + 1e-5f);
        g_scale[o] = inv;
        g_bias[o]  = rb[o] - rm[o] * inv;
    } else if (o < CO + CA) {
        int a = o - CO;
        float inv = ag[a] * rsqrtf(av[a] + 1e-5f);
        g_scale[o] = inv;
        g_bias[o]  = ab[a] - am[a] * inv;
    }
}

// ---------------------------------------------------------------------------
// Projection GEMM: out[o][p] = relu(scale[o] * sum_c W[o][c]*x[n][c][p] + bias[o])
// Stored transposed: g_feat[n][p][o] / g_q[n][p][o-256] (position-major rows).
// Block: 64o x 64p tile, 256 threads, 4x4 per thread, K chunks of 16.
// ---------------------------------------------------------------------------
__global__ __launch_bounds__(256) void proj_kernel(const float* __restrict__ x,
                                                   const float* __restrict__ reduc_w,
                                                   const float* __restrict__ att_w) {
    __shared__ float Ws[16][65];
    __shared__ float Xs[16][65];
    const int pb = blockIdx.x * 64;
    const int ob = blockIdx.y * 64;
    const int n  = blockIdx.z;
    const int t  = threadIdx.x;
    const int tx = t & 15, ty = t >> 4;
    const int o0 = ty * 4, p0 = tx * 4;

    const float* W = (ob < CO) ? (reduc_w + ob * CI) : (att_w + (ob - CO) * CI);
    const float* X = x + (n * CI) * HW + pb;

    float acc[4][4];
#pragma unroll
    for (int i = 0; i < 4; i++)
#pragma unroll
        for (int j = 0; j < 4; j++) acc[i][j] = 0.f;

    for (int kb = 0; kb < CI; kb += 16) {
        {   // load Ws[k][o]: each thread grabs float4 along k of one o-row
            int o  = t >> 2;
            int k0 = (t & 3) * 4;
            float4 w4 = *(const float4*)(W + o * CI + kb + k0);
            Ws[k0 + 0][o] = w4.x;
            Ws[k0 + 1][o] = w4.y;
            Ws[k0 + 2][o] = w4.z;
            Ws[k0 + 3][o] = w4.w;
        }
        {   // load Xs[k][p]: coalesced rows of x
            int p  = t & 63;
            int kk = t >> 6;
#pragma unroll
            for (int r = 0; r < 4; r++)
                Xs[kk + 4 * r][p] = X[(kb + kk + 4 * r) * HW + p];
        }
        __syncthreads();
#pragma unroll
        for (int k = 0; k < 16; k++) {
            float a[4], b[4];
#pragma unroll
            for (int i = 0; i < 4; i++) a[i] = Ws[k][o0 + i];
#pragma unroll
            for (int j = 0; j < 4; j++) b[j] = Xs[k][p0 + j];
#pragma unroll
            for (int i = 0; i < 4; i++)
#pragma unroll
                for (int j = 0; j < 4; j++)
                    acc[i][j] = fmaf(a[i], b[j], acc[i][j]);
        }
        __syncthreads();
    }

#pragma unroll
    for (int i = 0; i < 4; i++) {
        int o = ob + o0 + i;
        float sc = g_scale[o], bs = g_bias[o];
#pragma unroll
        for (int j = 0; j < 4; j++) {
            float v = fmaxf(fmaf(acc[i][j], sc, bs), 0.f);
            int p = pb + p0 + j;
            if (o < CO)
                g_feat[(n * HW + p) * CO + o] = v;
            else
                g_q[(n * HW + p) * CA + (o - CO)] = v;
        }
    }
}

// ---------------------------------------------------------------------------
// Flash self-attention (fp32 baseline):
//   S[i][j] = (q_i . q_j) * INVS + (mask_j - 1)*1e8
//   online softmax over j; out[n][c][i] = (sum_j P[i][j] feat[j][c]) / l_i * mask_i
// Block = (n, 64 i-positions), 256 threads.
//   Stage A: 4i x 4j per thread (tx -> i group, tg -> j group)
//   Stage B: 4i x 16c per thread (tx -> i group, tg -> c group)
// ---------------------------------------------------------------------------
__global__ __launch_bounds__(256) void flash_kernel(const float* __restrict__ mask,
                                                    float* __restrict__ out) {
    extern __shared__ float sm[];
    float* qi      = sm;                   // 64 x QSTR
    float* qj      = qi + BI * QSTR;       // 64 x QSTR
    float* fj      = qj + BJ * QSTR;       // 64 x 256
    float* ss      = fj + BJ * CO;         // 64 x SSTR (scores -> P)
    float* alpha_s = ss + BI * SSTR;       // 64
    float* l_s     = alpha_s + BI;         // 64
    float* mj      = l_s + BI;             // 64 additive mask term

    const int n  = blockIdx.y;
    const int ib = blockIdx.x * BI;
    const int t  = threadIdx.x;
    const int tx = t & 15, tg = t >> 4;

    // load q_i tile (padded-stride rows => conflict-free later reads)
    const float* qsrc = g_q + (n * HW + ib) * CA;
    for (int e = t; e < BI * CA; e += 256) {
        int i = e >> 7, k = e & 127;
        qi[i * QSTR + k] = qsrc[e];
    }

    float m_i = -1e30f, l_i = 0.f;
    float acc[16][4];
#pragma unroll
    for (int c = 0; c < 16; c++)
#pragma unroll
        for (int ii = 0; ii < 4; ii++) acc[c][ii] = 0.f;

    const float* maskn = mask + n * HW;

    for (int jb = 0; jb < HW; jb += BJ) {
        // --- stage 0: load tiles ---
        const float* qjs = g_q + (n * HW + jb) * CA;
        for (int e = t; e < BJ * CA; e += 256) {
            int j = e >> 7, k = e & 127;
            qj[j * QSTR + k] = qjs[e];
        }
        const float* fsrc = g_feat + (n * HW + jb) * CO;
        for (int e = t; e < BJ * CO; e += 256) fj[e] = fsrc[e];
        if (t < BJ) mj[t] = (maskn[jb + t] - 1.f) * 1e8f;
        __syncthreads();

        // --- stage A: S = qi . qj ---
        {
            const int i0 = tx * 4, j0 = tg * 4;
            float s[4][4];
#pragma unroll
            for (int ii = 0; ii < 4; ii++)
#pragma unroll
                for (int jj = 0; jj < 4; jj++) s[ii][jj] = 0.f;
#pragma unroll 8
            for (int k = 0; k < CA; k++) {
                float a[4], b[4];
#pragma unroll
                for (int ii = 0; ii < 4; ii++) a[ii] = qi[(i0 + ii) * QSTR + k];
#pragma unroll
                for (int jj = 0; jj < 4; jj++) b[jj] = qj[(j0 + jj) * QSTR + k];
#pragma unroll
                for (int ii = 0; ii < 4; ii++)
#pragma unroll
                    for (int jj = 0; jj < 4; jj++)
                        s[ii][jj] = fmaf(a[ii], b[jj], s[ii][jj]);
            }
#pragma unroll
            for (int ii = 0; ii < 4; ii++)
#pragma unroll
                for (int jj = 0; jj < 4; jj++)
                    ss[(i0 + ii) * SSTR + j0 + jj] = fmaf(s[ii][jj], INVS, mj[j0 + jj]);
        }
        __syncthreads();

        // --- online softmax (one row per thread, threads 0..63) ---
        if (t < BI) {
            float* row = ss + t * SSTR;
            float mt = row[0];
#pragma unroll 8
            for (int j = 1; j < BJ; j++) mt = fmaxf(mt, row[j]);
            float mnew  = fmaxf(m_i, mt);
            float alpha = __expf(m_i - mnew);
            float lsum  = 0.f;
#pragma unroll 8
            for (int j = 0; j < BJ; j++) {
                float p = __expf(row[j] - mnew);
                row[j] = p;
                lsum += p;
            }
            l_i = fmaf(l_i, alpha, lsum);
            m_i = mnew;
            alpha_s[t] = alpha;
        }
        __syncthreads();

        // --- stage B: acc = acc*alpha + P @ feat ---
        {
            const int i0 = tx * 4, c0 = tg * 16;
            float al[4];
#pragma unroll
            for (int ii = 0; ii < 4; ii++) al[ii] = alpha_s[i0 + ii];
#pragma unroll
            for (int c = 0; c < 16; c++)
#pragma unroll
                for (int ii = 0; ii < 4; ii++) acc[c][ii] *= al[ii];

#pragma unroll 2
            for (int j = 0; j < BJ; j++) {
                float p[4];
#pragma unroll
                for (int ii = 0; ii < 4; ii++) p[ii] = ss[(i0 + ii) * SSTR + j];
                const float4* fr = (const float4*)(fj + j * CO + c0);
#pragma unroll
                for (int q = 0; q < 4; q++) {
                    float4 f = fr[q];
#pragma unroll
                    for (int ii = 0; ii < 4; ii++) {
                        acc[4 * q + 0][ii] = fmaf(p[ii], f.x, acc[4 * q + 0][ii]);
                        acc[4 * q + 1][ii] = fmaf(p[ii], f.y, acc[4 * q + 1][ii]);
                        acc[4 * q + 2][ii] = fmaf(p[ii], f.z, acc[4 * q + 2][ii]);
                        acc[4 * q + 3][ii] = fmaf(p[ii], f.w, acc[4 * q + 3][ii]);
                    }
                }
            }
        }
        __syncthreads();
    }

    if (t < BI) l_s[t] = l_i;
    __syncthreads();

    // epilogue: normalize, apply output mask, write out[n][c][i] (float4 along i)
    {
        const int i0 = tx * 4, c0 = tg * 16;
        float rl[4], mk[4];
#pragma unroll
        for (int ii = 0; ii < 4; ii++) {
            rl[ii] = 1.f / l_s[i0 + ii];
            mk[ii] = maskn[ib + i0 + ii];
        }
#pragma unroll
        for (int c = 0; c < 16; c++) {
            float4 v;
            v.x = acc[c][0] * rl[0] * mk[0];
            v.y = acc[c][1] * rl[1] * mk[1];
            v.z = acc[c][2] * rl[2] * mk[2];
            v.w = acc[c][3] * rl[3] * mk[3];
            *(float4*)(out + (n * CO + (c0 + c)) * HW + ib + i0) = v;
        }
    }
}

// ---------------------------------------------------------------------------
extern "C" void kernel_launch(void* const* d_in, const int* in_sizes, int n_in,
                              void* d_out, int out_size) {
    const float* x           = (const float*)d_in[0];
    const float* mask        = (const float*)d_in[1];
    const float* reduc_w     = (const float*)d_in[2];
    const float* reduc_gamma = (const float*)d_in[3];
    const float* reduc_beta  = (const float*)d_in[4];
    const float* reduc_mean  = (const float*)d_in[5];
    const float* reduc_var   = (const float*)d_in[6];
    const float* att_w       = (const float*)d_in[7];
    const float* att_gamma   = (const float*)d_in[8];
    const float* att_beta    = (const float*)d_in[9];
    const float* att_mean    = (const float*)d_in[10];
    const float* att_var     = (const float*)d_in[11];
    float* out = (float*)d_out;

    prep_kernel<<<1, CO + CA>>>(reduc_gamma, reduc_beta, reduc_mean, reduc_var,
                                att_gamma, att_beta, att_mean, att_var);

    dim3 gproj(HW / 64, (CO + CA) / 64, NB);
    proj_kernel<<<gproj, 256>>>(x, reduc_w, att_w);

    int smem_bytes = (2 * BI * QSTR + BJ * CO + BI * SSTR + 3 * BI) * (int)sizeof(float);
    cudaFuncSetAttribute(flash_kernel, cudaFuncAttributeMaxDynamicSharedMemorySize, smem_bytes);
    dim3 gfl(HW / BI, NB);
    flash_kernel<<<gfl, 256, smem_bytes>>>(mask, out);
}

// round 3
// speedup vs baseline: 1.0127x; 1.0127x over previous
#include <cuda_runtime.h>

#define NB 8
#define HW 4096
#define CI 256
#define CA 128
#define CO 256
#define BI 64
#define BJ 64
#define QSTR 129
#define SSTR 65
// 1/(1e-8 + sqrt(128))
#define INVS 0.08838834764831843f

// Scratch (allocation-free: __device__ globals)
__device__ float g_q[NB * HW * CA];      // [n][pos][128]
__device__ float g_feat[NB * HW * CO];   // [n][pos][256]
__device__ float g_scale[CO + CA];
__device__ float g_bias[CO + CA];

// ---------------------------------------------------------------------------
// Fold BN into per-channel scale/bias: y = conv*scale + bias, then ReLU.
// Channels [0,256) = reduc (feat), [256,384) = att (q).
// ---------------------------------------------------------------------------
__global__ void prep_kernel(const float* __restrict__ rg, const float* __restrict__ rb,
                            const float* __restrict__ rm, const float* __restrict__ rv,
                            const float* __restrict__ ag, const float* __restrict__ ab,
                            const float* __restrict__ am, const float* __restrict__ av) {
    int o = threadIdx.x;
    if (o < CO) {
        float inv = rg[o] * rsqrtf(rv[o] + 1e-5f);
        g_scale[o] = inv;
        g_bias[o]  = rb[o] - rm[o] * inv;
    } else if (o < CO + CA) {
        int a = o - CO;
        float inv = ag[a] * rsqrtf(av[a] + 1e-5f);
        g_scale[o] = inv;
        g_bias[o]  = ab[a] - am[a] * inv;
    }
}

// ---------------------------------------------------------------------------
// Projection GEMM: out[o][p] = relu(scale[o] * sum_c W[o][c]*x[n][c][p] + bias[o])
// Stored transposed: g_feat[n][p][o] / g_q[n][p][o-256] (position-major rows).
// Block: 64o x 64p tile, 256 threads, 4x4 per thread, K chunks of 16.
// ---------------------------------------------------------------------------
__global__ __launch_bounds__(256) void proj_kernel(const float* __restrict__ x,
                                                   const float* __restrict__ reduc_w,
                                                   const float* __restrict__ att_w) {
    __shared__ float Ws[16][65];
    __shared__ float Xs[16][65];
    const int pb = blockIdx.x * 64;
    const int ob = blockIdx.y * 64;
    const int n  = blockIdx.z;
    const int t  = threadIdx.x;
    const int tx = t & 15, ty = t >> 4;
    const int o0 = ty * 4, p0 = tx * 4;

    const float* W = (ob < CO) ? (reduc_w + ob * CI) : (att_w + (ob - CO) * CI);
    const float* X = x + (n * CI) * HW + pb;

    float acc[4][4];
#pragma unroll
    for (int i = 0; i < 4; i++)
#pragma unroll
        for (int j = 0; j < 4; j++) acc[i][j] = 0.f;

    for (int kb = 0; kb < CI; kb += 16) {
        {   // load Ws[k][o]: each thread grabs float4 along k of one o-row
            int o  = t >> 2;
            int k0 = (t & 3) * 4;
            float4 w4 = *(const float4*)(W + o * CI + kb + k0);
            Ws[k0 + 0][o] = w4.x;
            Ws[k0 + 1][o] = w4.y;
            Ws[k0 + 2][o] = w4.z;
            Ws[k0 + 3][o] = w4.w;
        }
        {   // load Xs[k][p]: coalesced rows of x
            int p  = t & 63;
            int kk = t >> 6;
#pragma unroll
            for (int r = 0; r < 4; r++)
                Xs[kk + 4 * r][p] = X[(kb + kk + 4 * r) * HW + p];
        }
        __syncthreads();
#pragma unroll
        for (int k = 0; k < 16; k++) {
            float a[4], b[4];
#pragma unroll
            for (int i = 0; i < 4; i++) a[i] = Ws[k][o0 + i];
#pragma unroll
            for (int j = 0; j < 4; j++) b[j] = Xs[k][p0 + j];
#pragma unroll
            for (int i = 0; i < 4; i++)
#pragma unroll
                for (int j = 0; j < 4; j++)
                    acc[i][j] = fmaf(a[i], b[j], acc[i][j]);
        }
        __syncthreads();
    }

#pragma unroll
    for (int i = 0; i < 4; i++) {
        int o = ob + o0 + i;
        float sc = g_scale[o], bs = g_bias[o];
#pragma unroll
        for (int j = 0; j < 4; j++) {
            float v = fmaxf(fmaf(acc[i][j], sc, bs), 0.f);
            int p = pb + p0 + j;
            if (o < CO)
                g_feat[(n * HW + p) * CO + o] = v;
            else
                g_q[(n * HW + p) * CA + (o - CO)] = v;
        }
    }
}

// ---------------------------------------------------------------------------
// Flash self-attention (fp32 baseline):
//   S[i][j] = (q_i . q_j) * INVS + (mask_j - 1)*1e8
//   online softmax over j; out[n][c][i] = (sum_j P[i][j] feat[j][c]) / l_i * mask_i
// Block = (n, 64 i-positions), 256 threads.
//   Stage A: 4i x 4j per thread (tx -> i group, tg -> j group)
//   Stage B: 4i x 16c per thread (tx -> i group, tg -> c group)
// ---------------------------------------------------------------------------
__global__ __launch_bounds__(256) void flash_kernel(const float* __restrict__ mask,
                                                    float* __restrict__ out) {
    extern __shared__ float sm[];
    float* qi      = sm;                   // 64 x QSTR
    float* qj      = qi + BI * QSTR;       // 64 x QSTR
    float* fj      = qj + BJ * QSTR;       // 64 x 256
    float* ss      = fj + BJ * CO;         // 64 x SSTR (scores -> P)
    float* alpha_s = ss + BI * SSTR;       // 64
    float* l_s     = alpha_s + BI;         // 64
    float* mj      = l_s + BI;             // 64 additive mask term

    const int n  = blockIdx.y;
    const int ib = blockIdx.x * BI;
    const int t  = threadIdx.x;
    const int tx = t & 15, tg = t >> 4;

    // load q_i tile (padded-stride rows => conflict-free later reads)
    const float* qsrc = g_q + (n * HW + ib) * CA;
    for (int e = t; e < BI * CA; e += 256) {
        int i = e >> 7, k = e & 127;
        qi[i * QSTR + k] = qsrc[e];
    }

    float m_i = -1e30f, l_i = 0.f;
    float acc[16][4];
#pragma unroll
    for (int c = 0; c < 16; c++)
#pragma unroll
        for (int ii = 0; ii < 4; ii++) acc[c][ii] = 0.f;

    const float* maskn = mask + n * HW;

    for (int jb = 0; jb < HW; jb += BJ) {
        // --- stage 0: load tiles ---
        const float* qjs = g_q + (n * HW + jb) * CA;
        for (int e = t; e < BJ * CA; e += 256) {
            int j = e >> 7, k = e & 127;
            qj[j * QSTR + k] = qjs[e];
        }
        const float* fsrc = g_feat + (n * HW + jb) * CO;
        for (int e = t; e < BJ * CO; e += 256) fj[e] = fsrc[e];
        if (t < BJ) mj[t] = (maskn[jb + t] - 1.f) * 1e8f;
        __syncthreads();

        // --- stage A: S = qi . qj ---
        {
            const int i0 = tx * 4, j0 = tg * 4;
            float s[4][4];
#pragma unroll
            for (int ii = 0; ii < 4; ii++)
#pragma unroll
                for (int jj = 0; jj < 4; jj++) s[ii][jj] = 0.f;
#pragma unroll 8
            for (int k = 0; k < CA; k++) {
                float a[4], b[4];
#pragma unroll
                for (int ii = 0; ii < 4; ii++) a[ii] = qi[(i0 + ii) * QSTR + k];
#pragma unroll
                for (int jj = 0; jj < 4; jj++) b[jj] = qj[(j0 + jj) * QSTR + k];
#pragma unroll
                for (int ii = 0; ii < 4; ii++)
#pragma unroll
                    for (int jj = 0; jj < 4; jj++)
                        s[ii][jj] = fmaf(a[ii], b[jj], s[ii][jj]);
            }
#pragma unroll
            for (int ii = 0; ii < 4; ii++)
#pragma unroll
                for (int jj = 0; jj < 4; jj++)
                    ss[(i0 + ii) * SSTR + j0 + jj] = fmaf(s[ii][jj], INVS, mj[j0 + jj]);
        }
        __syncthreads();

        // --- online softmax (one row per thread, threads 0..63) ---
        if (t < BI) {
            float* row = ss + t * SSTR;
            float mt = row[0];
#pragma unroll 8
            for (int j = 1; j < BJ; j++) mt = fmaxf(mt, row[j]);
            float mnew  = fmaxf(m_i, mt);
            float alpha = __expf(m_i - mnew);
            float lsum  = 0.f;
#pragma unroll 8
            for (int j = 0; j < BJ; j++) {
                float p = __expf(row[j] - mnew);
                row[j] = p;
                lsum += p;
            }
            l_i = fmaf(l_i, alpha, lsum);
            m_i = mnew;
            alpha_s[t] = alpha;
        }
        __syncthreads();

        // --- stage B: acc = acc*alpha + P @ feat ---
        {
            const int i0 = tx * 4, c0 = tg * 16;
            float al[4];
#pragma unroll
            for (int ii = 0; ii < 4; ii++) al[ii] = alpha_s[i0 + ii];
#pragma unroll
            for (int c = 0; c < 16; c++)
#pragma unroll
                for (int ii = 0; ii < 4; ii++) acc[c][ii] *= al[ii];

#pragma unroll 2
            for (int j = 0; j < BJ; j++) {
                float p[4];
#pragma unroll
                for (int ii = 0; ii < 4; ii++) p[ii] = ss[(i0 + ii) * SSTR + j];
                const float4* fr = (const float4*)(fj + j * CO + c0);
#pragma unroll
                for (int q = 0; q < 4; q++) {
                    float4 f = fr[q];
#pragma unroll
                    for (int ii = 0; ii < 4; ii++) {
                        acc[4 * q + 0][ii] = fmaf(p[ii], f.x, acc[4 * q + 0][ii]);
                        acc[4 * q + 1][ii] = fmaf(p[ii], f.y, acc[4 * q + 1][ii]);
                        acc[4 * q + 2][ii] = fmaf(p[ii], f.z, acc[4 * q + 2][ii]);
                        acc[4 * q + 3][ii] = fmaf(p[ii], f.w, acc[4 * q + 3][ii]);
                    }
                }
            }
        }
        __syncthreads();
    }

    if (t < BI) l_s[t] = l_i;
    __syncthreads();

    // epilogue: normalize, apply output mask, write out[n][c][i] (float4 along i)
    {
        const int i0 = tx * 4, c0 = tg * 16;
        float rl[4], mk[4];
#pragma unroll
        for (int ii = 0; ii < 4; ii++) {
            rl[ii] = 1.f / l_s[i0 + ii];
            mk[ii] = maskn[ib + i0 + ii];
        }
#pragma unroll
        for (int c = 0; c < 16; c++) {
            float4 v;
            v.x = acc[c][0] * rl[0] * mk[0];
            v.y = acc[c][1] * rl[1] * mk[1];
            v.z = acc[c][2] * rl[2] * mk[2];
            v.w = acc[c][3] * rl[3] * mk[3];
            *(float4*)(out + (n * CO + (c0 + c)) * HW + ib + i0) = v;
        }
    }
}

// ---------------------------------------------------------------------------
extern "C" void kernel_launch(void* const* d_in, const int* in_sizes, int n_in,
                              void* d_out, int out_size) {
    const float* x           = (const float*)d_in[0];
    const float* mask        = (const float*)d_in[1];
    const float* reduc_w     = (const float*)d_in[2];
    const float* reduc_gamma = (const float*)d_in[3];
    const float* reduc_beta  = (const float*)d_in[4];
    const float* reduc_mean  = (const float*)d_in[5];
    const float* reduc_var   = (const float*)d_in[6];
    const float* att_w       = (const float*)d_in[7];
    const float* att_gamma   = (const float*)d_in[8];
    const float* att_beta    = (const float*)d_in[9];
    const float* att_mean    = (const float*)d_in[10];
    const float* att_var     = (const float*)d_in[11];
    float* out = (float*)d_out;

    prep_kernel<<<1, CO + CA>>>(reduc_gamma, reduc_beta, reduc_mean, reduc_var,
                                att_gamma, att_beta, att_mean, att_var);

    dim3 gproj(HW / 64, (CO + CA) / 64, NB);
    proj_kernel<<<gproj, 256>>>(x, reduc_w, att_w);

    int smem_bytes = (2 * BI * QSTR + BJ * CO + BI * SSTR + 3 * BI) * (int)sizeof(float);
    cudaFuncSetAttribute(flash_kernel, cudaFuncAttributeMaxDynamicSharedMemorySize, smem_bytes);
    dim3 gfl(HW / BI, NB);
    flash_kernel<<<gfl, 256, smem_bytes>>>(mask, out);
}

// round 6
// speedup vs baseline: 5.4265x; 5.3587x over previous
#include <cuda_runtime.h>
#include <cuda_bf16.h>
#include <cuda_fp16.h>
#include <cstdint>

#define NB 8
#define HW 4096
#define CI 256
#define CA 128
#define CO 256
#define INVS 0.08838834764831843f
#define PSC  0.015625f     // 2^-6 P scaling (fp16 headroom)
#define PSCI 64.0f

// flash SMEM layout (byte offsets, 16B-aligned)
#define QJ_STR   272       // 128 bf16 = 256B data + pad
#define FEAT_STR 144       // 64 fp16 = 128B data + pad
#define P_STR    144
#define QJ_BUF   17408     // 64*272
#define FEAT_BUF 36864     // 256*144
#define QJH_OFF  0
#define QJL_OFF  34816
#define FEAT_OFF 69632
#define P_OFF    143360    // 64*144 = 9216
#define MJ_OFF   152576    // 2*256
#define LRED_OFF 153088    // 256
#define SMEM_TOTAL 153600

__device__ __nv_bfloat16 g_qhi[NB * HW * CA];
__device__ __nv_bfloat16 g_qlo[NB * HW * CA];
__device__ __half g_featT[(size_t)NB * CO * HW];
__device__ float g_scale[CO + CA];
__device__ float g_bias[CO + CA];

__device__ __forceinline__ uint32_t smem_u32(const void* p) {
    uint32_t a;
    asm("{ .reg .u64 t; cvta.to.shared.u64 t, %1; cvt.u32.u64 %0, t; }" : "=r"(a) : "l"(p));
    return a;
}
#define CP16(dst, src) asm volatile("cp.async.cg.shared.global [%0], [%1], 16;" :: "r"(dst), "l"(src))
#define CP_COMMIT()    asm volatile("cp.async.commit_group;" ::: "memory")
#define CP_WAIT1()     asm volatile("cp.async.wait_group 1;" ::: "memory")
#define CP_WAIT0()     asm volatile("cp.async.wait_group 0;" ::: "memory")

__device__ __forceinline__ void mma_bf16(float* d, const uint32_t* a, const uint32_t* b) {
    asm volatile("mma.sync.aligned.m16n8k16.row.col.f32.bf16.bf16.f32 "
        "{%0,%1,%2,%3}, {%4,%5,%6,%7}, {%8,%9}, {%0,%1,%2,%3};"
        : "+f"(d[0]), "+f"(d[1]), "+f"(d[2]), "+f"(d[3])
        : "r"(a[0]), "r"(a[1]), "r"(a[2]), "r"(a[3]), "r"(b[0]), "r"(b[1]));
}
__device__ __forceinline__ void mma_f16(float* d, const uint32_t* a, const uint32_t* b) {
    asm volatile("mma.sync.aligned.m16n8k16.row.col.f32.f16.f16.f32 "
        "{%0,%1,%2,%3}, {%4,%5,%6,%7}, {%8,%9}, {%0,%1,%2,%3};"
        : "+f"(d[0]), "+f"(d[1]), "+f"(d[2]), "+f"(d[3])
        : "r"(a[0]), "r"(a[1]), "r"(a[2]), "r"(a[3]), "r"(b[0]), "r"(b[1]));
}

__global__ void prep_kernel(const float* __restrict__ rg, const float* __restrict__ rb,
                            const float* __restrict__ rm, const float* __restrict__ rv,
                            const float* __restrict__ ag, const float* __restrict__ ab,
                            const float* __restrict__ am, const float* __restrict__ av) {
    int o = threadIdx.x;
    if (o < CO) {
        float inv = rg[o] * rsqrtf(rv[o] + 1e-5f);
        g_scale[o] = inv; g_bias[o] = rb[o] - rm[o] * inv;
    } else if (o < CO + CA) {
        int a = o - CO;
        float inv = ag[a] * rsqrtf(av[a] + 1e-5f);
        g_scale[o] = inv; g_bias[o] = ab[a] - am[a] * inv;
    }
}

// conv1x1 + BN + ReLU -> fp16 featT[n][c][pos] and hi/lo-split bf16 q[n][pos][k]
__global__ __launch_bounds__(256) void proj_kernel(const float* __restrict__ x,
                                                   const float* __restrict__ reduc_w,
                                                   const float* __restrict__ att_w) {
    __shared__ float Ws[16][65];
    __shared__ float Xs[16][65];
    __shared__ float tbuf[64][65];
    const int pb = blockIdx.x * 64, ob = blockIdx.y * 64, n = blockIdx.z;
    const int t = threadIdx.x, tx = t & 15, ty = t >> 4;
    const int o0 = ty * 4, p0 = tx * 4;
    const float* W = (ob < CO) ? (reduc_w + ob * CI) : (att_w + (ob - CO) * CI);
    const float* X = x + (size_t)(n * CI) * HW + pb;

    float acc[4][4];
#pragma unroll
    for (int i = 0; i < 4; i++)
#pragma unroll
        for (int j = 0; j < 4; j++) acc[i][j] = 0.f;

    for (int kb = 0; kb < CI; kb += 16) {
        {
            int o = t >> 2, k0 = (t & 3) * 4;
            float4 w4 = *(const float4*)(W + o * CI + kb + k0);
            Ws[k0][o] = w4.x; Ws[k0+1][o] = w4.y; Ws[k0+2][o] = w4.z; Ws[k0+3][o] = w4.w;
        }
        {
            int p = t & 63, kk = t >> 6;
#pragma unroll
            for (int r = 0; r < 4; r++)
                Xs[kk + 4*r][p] = X[(size_t)(kb + kk + 4*r) * HW + p];
        }
        __syncthreads();
#pragma unroll
        for (int k = 0; k < 16; k++) {
            float a[4], b[4];
#pragma unroll
            for (int i = 0; i < 4; i++) a[i] = Ws[k][o0 + i];
#pragma unroll
            for (int j = 0; j < 4; j++) b[j] = Xs[k][p0 + j];
#pragma unroll
            for (int i = 0; i < 4; i++)
#pragma unroll
                for (int j = 0; j < 4; j++)
                    acc[i][j] = fmaf(a[i], b[j], acc[i][j]);
        }
        __syncthreads();
    }

    if (ob < CO) {
#pragma unroll
        for (int i = 0; i < 4; i++) {
            int o = ob + o0 + i;
            float sc = g_scale[o], bs = g_bias[o];
            float v0 = fmaxf(fmaf(acc[i][0], sc, bs), 0.f);
            float v1 = fmaxf(fmaf(acc[i][1], sc, bs), 0.f);
            float v2 = fmaxf(fmaf(acc[i][2], sc, bs), 0.f);
            float v3 = fmaxf(fmaf(acc[i][3], sc, bs), 0.f);
            __half2 h0 = __floats2half2_rn(v0, v1);
            __half2 h1 = __floats2half2_rn(v2, v3);
            uint2 pk = make_uint2(*(uint32_t*)&h0, *(uint32_t*)&h1);
            *(uint2*)(g_featT + ((size_t)n * CO + o) * HW + pb + p0) = pk;
        }
    } else {
#pragma unroll
        for (int i = 0; i < 4; i++) {
            float sc = g_scale[ob + o0 + i], bs = g_bias[ob + o0 + i];
#pragma unroll
            for (int j = 0; j < 4; j++)
                tbuf[o0 + i][p0 + j] = fmaxf(fmaf(acc[i][j], sc, bs), 0.f);
        }
        __syncthreads();
        if (t < 128) {
            int p = t & 63, half = t >> 6;
            __nv_bfloat16* dst = (half ? g_qlo : g_qhi) +
                                 ((size_t)(n * HW + pb + p)) * CA + (ob - CO);
#pragma unroll
            for (int k0 = 0; k0 < 64; k0 += 8) {
                uint32_t pk[4];
#pragma unroll
                for (int q = 0; q < 4; q++) {
                    float va = tbuf[k0 + 2*q][p], vb = tbuf[k0 + 2*q + 1][p];
                    __nv_bfloat16 ha = __float2bfloat16(va), hb = __float2bfloat16(vb);
                    __nv_bfloat162 bb;
                    if (half) bb = __floats2bfloat162_rn(va - __bfloat162float(ha),
                                                         vb - __bfloat162float(hb));
                    else { bb.x = ha; bb.y = hb; }
                    pk[q] = *(uint32_t*)&bb;
                }
                *(uint4*)(dst + k0) = make_uint4(pk[0], pk[1], pk[2], pk[3]);
            }
        }
    }
}

// flash attention on HMMA (mma.sync m16n8k16)
__global__ __launch_bounds__(256, 1) void flash_kernel(const float* __restrict__ mask,
                                                       float* __restrict__ out) {
    extern __shared__ __align__(16) char sm[];
    const uint32_t smb = smem_u32(sm);
    const int n = blockIdx.y, ib = blockIdx.x * 64;
    const int tid = threadIdx.x, w = tid >> 5, lane = tid & 31;
    const int gid = lane >> 2, tig = lane & 3;
    const int g = w >> 1, jh = w & 1;

    // Qi A-fragments (hi/lo) in registers for the whole j loop
    uint32_t ah[8][4], al[8][4];
    {
        const size_t r0 = (size_t)(n * HW + ib + g * 16 + gid) * CA;
        const size_t r1 = r0 + 8 * CA;
#pragma unroll
        for (int ks = 0; ks < 8; ks++) {
            int c0 = ks * 16 + 2 * tig;
            ah[ks][0] = *(const uint32_t*)(g_qhi + r0 + c0);
            ah[ks][1] = *(const uint32_t*)(g_qhi + r1 + c0);
            ah[ks][2] = *(const uint32_t*)(g_qhi + r0 + c0 + 8);
            ah[ks][3] = *(const uint32_t*)(g_qhi + r1 + c0 + 8);
            al[ks][0] = *(const uint32_t*)(g_qlo + r0 + c0);
            al[ks][1] = *(const uint32_t*)(g_qlo + r1 + c0);
            al[ks][2] = *(const uint32_t*)(g_qlo + r0 + c0 + 8);
            al[ks][3] = *(const uint32_t*)(g_qlo + r1 + c0 + 8);
        }
    }

    auto prefetch = [&](int t) {
        const int buf = t & 1, jb = t * 64;
        const uint32_t qh = smb + QJH_OFF + buf * QJ_BUF;
        const uint32_t ql = smb + QJL_OFF + buf * QJ_BUF;
#pragma unroll
        for (int it = 0; it < 4; it++) {           // FIX: full 256B rows (was it<2 -> half)
            int e = tid + it * 256, row = e >> 4, ch = e & 15;
            size_t go = (size_t)(n * HW + jb + row) * CA + ch * 8;
            CP16(qh + row * QJ_STR + ch * 16, (const char*)(g_qhi + go));
            CP16(ql + row * QJ_STR + ch * 16, (const char*)(g_qlo + go));
        }
        const uint32_t fb = smb + FEAT_OFF + buf * FEAT_BUF;
#pragma unroll
        for (int it = 0; it < 8; it++) {
            int e = tid + it * 256, row = e >> 3, ch = e & 7;
            CP16(fb + row * FEAT_STR + ch * 16,
                 (const char*)(g_featT + ((size_t)n * CO + row) * HW + jb + ch * 8));
        }
        if (tid < 16)
            CP16(smb + MJ_OFF + buf * 256 + tid * 16, (const char*)(mask + n * HW + jb + tid * 4));
        CP_COMMIT();
    };

    float dacc[8][2][4];
#pragma unroll
    for (int mt = 0; mt < 8; mt++)
#pragma unroll
        for (int nb = 0; nb < 2; nb++)
#pragma unroll
            for (int r = 0; r < 4; r++) dacc[mt][nb][r] = 0.f;
    float l0 = 0.f, l1 = 0.f;

    prefetch(0);

    for (int t = 0; t < 64; t++) {
        __syncthreads();                    // prior reads of buf (t+1)&1 done
        if (t < 63) { prefetch(t + 1); CP_WAIT1(); } else { CP_WAIT0(); }
        __syncthreads();                    // buf t visible CTA-wide
        const int buf = t & 1;

        // ---- QK: S[16i x 32j] via 3 bf16 passes (hh, hl, lh) ----
        float s[4][4];
#pragma unroll
        for (int jq = 0; jq < 4; jq++)
#pragma unroll
            for (int r = 0; r < 4; r++) s[jq][r] = 0.f;
#pragma unroll
        for (int pass = 0; pass < 3; pass++) {
            const char* qj = sm + ((pass == 1) ? QJL_OFF : QJH_OFF) + buf * QJ_BUF;
#pragma unroll
            for (int ks = 0; ks < 8; ks++) {
#pragma unroll
                for (int jq = 0; jq < 4; jq++) {
                    const char* rp = qj + (jh * 32 + jq * 8 + gid) * QJ_STR + (ks * 16 + 2 * tig) * 2;
                    uint32_t b[2];
                    b[0] = *(const uint32_t*)rp;
                    b[1] = *(const uint32_t*)(rp + 16);
                    mma_bf16(s[jq], (pass == 2) ? al[ks] : ah[ks], b);
                }
            }
        }

        // ---- softmax (no-max; scores bounded) -> scaled fp16 P in SMEM ----
        const float* mjb = (const float*)(sm + MJ_OFF + buf * 256);
        char* P = sm + P_OFF;
#pragma unroll
        for (int jq = 0; jq < 4; jq++) {
            int j8 = jh * 32 + jq * 8;
            float m0 = (mjb[j8 + 2 * tig]     - 1.f) * 1e8f;
            float m1 = (mjb[j8 + 2 * tig + 1] - 1.f) * 1e8f;
            float p0 = __expf(fmaf(s[jq][0], INVS, m0));
            float p1 = __expf(fmaf(s[jq][1], INVS, m1));
            float p2 = __expf(fmaf(s[jq][2], INVS, m0));
            float p3 = __expf(fmaf(s[jq][3], INVS, m1));
            l0 += p0 + p1; l1 += p2 + p3;
            __half2 q01 = __floats2half2_rn(p0 * PSC, p1 * PSC);
            __half2 q23 = __floats2half2_rn(p2 * PSC, p3 * PSC);
            *(uint32_t*)(P + (g * 16 + gid)     * P_STR + (j8 + 2 * tig) * 2) = *(uint32_t*)&q01;
            *(uint32_t*)(P + (g * 16 + 8 + gid) * P_STR + (j8 + 2 * tig) * 2) = *(uint32_t*)&q23;
        }
        __syncthreads();                    // P complete

        // ---- PV: dacc[c16 x i16] += feat @ P^T (warp's 128-c half) ----
        uint32_t bp[4][2][2];
#pragma unroll
        for (int ks = 0; ks < 4; ks++)
#pragma unroll
            for (int nb = 0; nb < 2; nb++) {
                const char* rp = P + (g * 16 + nb * 8 + gid) * P_STR + (ks * 16 + 2 * tig) * 2;
                bp[ks][nb][0] = *(const uint32_t*)rp;
                bp[ks][nb][1] = *(const uint32_t*)(rp + 16);
            }
        const char* fbb = sm + FEAT_OFF + buf * FEAT_BUF;
#pragma unroll
        for (int ks = 0; ks < 4; ks++) {
#pragma unroll
            for (int mt = 0; mt < 8; mt++) {
                const char* ap = fbb + (jh * 128 + mt * 16 + gid) * FEAT_STR + (ks * 16 + 2 * tig) * 2;
                uint32_t a[4];
                a[0] = *(const uint32_t*)ap;
                a[1] = *(const uint32_t*)(ap + 8 * FEAT_STR);
                a[2] = *(const uint32_t*)(ap + 16);
                a[3] = *(const uint32_t*)(ap + 8 * FEAT_STR + 16);
                mma_f16(dacc[mt][0], a, bp[ks][0]);
                mma_f16(dacc[mt][1], a, bp[ks][1]);
            }
        }
    }

    // ---- l reduction (quad shuffle + cross-warp-pair via SMEM) ----
    l0 += __shfl_xor_sync(0xFFFFFFFFu, l0, 1);
    l0 += __shfl_xor_sync(0xFFFFFFFFu, l0, 2);
    l1 += __shfl_xor_sync(0xFFFFFFFFu, l1, 1);
    l1 += __shfl_xor_sync(0xFFFFFFFFu, l1, 2);
    float* lred = (float*)(sm + LRED_OFF);
    __syncthreads();
    if (jh == 0 && tig == 0) { lred[g * 16 + gid] = l0; lred[g * 16 + 8 + gid] = l1; }
    __syncthreads();
    if (jh == 1 && tig == 0) { lred[g * 16 + gid] += l0; lred[g * 16 + 8 + gid] += l1; }
    __syncthreads();

    // ---- epilogue: out[c][i] = dacc * 64 / l * mask_i ----
#pragma unroll
    for (int nb = 0; nb < 2; nb++) {
        int i0 = g * 16 + nb * 8 + 2 * tig;
        float r0 = mask[n * HW + ib + i0]     * PSCI / fmaxf(lred[i0],     1e-30f);
        float r1 = mask[n * HW + ib + i0 + 1] * PSCI / fmaxf(lred[i0 + 1], 1e-30f);
#pragma unroll
        for (int mt = 0; mt < 8; mt++) {
            int c = jh * 128 + mt * 16 + gid;
            float2 v0 = make_float2(dacc[mt][nb][0] * r0, dacc[mt][nb][1] * r1);
            float2 v1 = make_float2(dacc[mt][nb][2] * r0, dacc[mt][nb][3] * r1);
            *(float2*)(out + ((size_t)(n * CO + c))     * HW + ib + i0) = v0;
            *(float2*)(out + ((size_t)(n * CO + c + 8)) * HW + ib + i0) = v1;
        }
    }
}

extern "C" void kernel_launch(void* const* d_in, const int* in_sizes, int n_in,
                              void* d_out, int out_size) {
    const float* x    = (const float*)d_in[0];
    const float* mask = (const float*)d_in[1];
    prep_kernel<<<1, CO + CA>>>((const float*)d_in[3], (const float*)d_in[4],
                                (const float*)d_in[5], (const float*)d_in[6],
                                (const float*)d_in[8], (const float*)d_in[9],
                                (const float*)d_in[10], (const float*)d_in[11]);
    dim3 gproj(HW / 64, (CO + CA) / 64, NB);
    proj_kernel<<<gproj, 256>>>(x, (const float*)d_in[2], (const float*)d_in[7]);

    cudaFuncSetAttribute(flash_kernel, cudaFuncAttributeMaxDynamicSharedMemorySize, SMEM_TOTAL);
    dim3 gfl(HW / 64, NB);
    flash_kernel<<<gfl, 256, SMEM_TOTAL>>>(mask, (float*)d_out);
}